// round 4
// baseline (speedup 1.0000x reference)
#include <cuda_runtime.h>

// out[i,p] = sum_{m,n} A[i,m] * B[i,n] * C[m,n,p]   (M1=M2=MP=5)
//
// Round-4: shared-memory staging to decouple MLP from register pressure.
//  Phase 1: CTA cooperatively loads 1024 edges of A and B as LDG.128 (10/thread).
//  Phase 2: each thread computes 4 interleaved edges from shared (conflict-free,
//           lane stride = 5 floats), overwrites its own bufA slots with results.
//  Phase 3: cooperative STG.128 store-out.
// Registers only hold one edge-pair working set -> 5 CTAs/SM (smem-limited),
// 40 warps. Round 3 was latency-bound: narrow strided LDG.64s + 32-warp cap.

#define M1 5
#define M2 5
#define MP 5
#define TPB 256
#define EPT 4
#define EDGES_PER_CTA (TPB * EPT)            // 1024
#define CHUNK_FLOATS  (EDGES_PER_CTA * 5)    // 5120
#define CHUNK_F4      (CHUNK_FLOATS / 4)     // 1280
#define F4_PER_THREAD (CHUNK_F4 / TPB)       // 5

__global__ __launch_bounds__(TPB, 5)
void cg_combine_kernel(const float* __restrict__ A,
                       const float* __restrict__ B,
                       const float* __restrict__ C,
                       float* __restrict__ out,
                       long long n_edges)
{
    __shared__ float bufA[CHUNK_FLOATS];
    __shared__ float bufB[CHUNK_FLOATS];
    __shared__ float csT[M1][MP][8];         // csT[m][p][n], 32B-aligned cols

    int t = threadIdx.x;
    long long cta_base = (long long)blockIdx.x * EDGES_PER_CTA;

    if (t < M1 * M2 * MP) {
        int m = t / 25, n = (t / 5) % 5, p = t % 5;
        csT[m][p][n] = C[t];                 // t = (m*5 + n)*5 + p
    }

    if (cta_base + EDGES_PER_CTA <= n_edges) {
        // ---- phase 1: cooperative coalesced load (LDG.128 x10, batched) ----
        const float4* gA = reinterpret_cast<const float4*>(A + cta_base * 5);
        const float4* gB = reinterpret_cast<const float4*>(B + cta_base * 5);
        float4* s4A = reinterpret_cast<float4*>(bufA);
        float4* s4B = reinterpret_cast<float4*>(bufB);

        float4 ra[F4_PER_THREAD], rb[F4_PER_THREAD];
#pragma unroll
        for (int i = 0; i < F4_PER_THREAD; i++) ra[i] = __ldcs(gA + t + TPB * i);
#pragma unroll
        for (int i = 0; i < F4_PER_THREAD; i++) rb[i] = __ldcs(gB + t + TPB * i);
#pragma unroll
        for (int i = 0; i < F4_PER_THREAD; i++) {
            s4A[t + TPB * i] = ra[i];
            s4B[t + TPB * i] = rb[i];
        }
        __syncthreads();

        // ---- phase 2: compute 4 interleaved edges (2 pairs) ----
#pragma unroll
        for (int h = 0; h < 2; h++) {
            int e0 = t + 512 * h;            // lane stride 5 floats: no conflicts
            int e1 = e0 + 256;

            float a0[5], a1[5], b0[5], b1[5], acc0[5], acc1[5];
#pragma unroll
            for (int k = 0; k < 5; k++) {
                a0[k] = bufA[e0 * 5 + k];  a1[k] = bufA[e1 * 5 + k];
                b0[k] = bufB[e0 * 5 + k];  b1[k] = bufB[e1 * 5 + k];
                acc0[k] = 0.0f;            acc1[k] = 0.0f;
            }

#pragma unroll
            for (int m = 0; m < M1; m++) {
#pragma unroll
                for (int p = 0; p < MP; p++) {
                    float4 c03 = *reinterpret_cast<const float4*>(&csT[m][p][0]);
                    float  c4  = csT[m][p][4];

                    float d0 = c03.x * b0[0];
                    float d1 = c03.x * b1[0];
                    d0 = fmaf(b0[1], c03.y, d0);  d1 = fmaf(b1[1], c03.y, d1);
                    d0 = fmaf(b0[2], c03.z, d0);  d1 = fmaf(b1[2], c03.z, d1);
                    d0 = fmaf(b0[3], c03.w, d0);  d1 = fmaf(b1[3], c03.w, d1);
                    d0 = fmaf(b0[4], c4,    d0);  d1 = fmaf(b1[4], c4,    d1);

                    acc0[p] = fmaf(a0[m], d0, acc0[p]);
                    acc1[p] = fmaf(a1[m], d1, acc1[p]);
                }
            }

            // overwrite this thread's own A slots with the results (private)
#pragma unroll
            for (int k = 0; k < 5; k++) {
                bufA[e0 * 5 + k] = acc0[k];
                bufA[e1 * 5 + k] = acc1[k];
            }
        }
        __syncthreads();

        // ---- phase 3: cooperative coalesced store (STG.128 x5) ----
        float4* gO = reinterpret_cast<float4*>(out + cta_base * 5);
#pragma unroll
        for (int i = 0; i < F4_PER_THREAD; i++)
            __stcs(gO + t + TPB * i, s4A[t + TPB * i]);
    } else {
        // ---- tail CTA (uniform branch): scalar bounds-checked path ----
        __syncthreads();
        for (long long e = cta_base + t; e < n_edges; e += TPB) {
            float a[5], b[5];
#pragma unroll
            for (int k = 0; k < 5; k++) { a[k] = A[e * 5 + k]; b[k] = B[e * 5 + k]; }
#pragma unroll
            for (int p = 0; p < MP; p++) {
                float s = 0.0f;
#pragma unroll
                for (int m = 0; m < M1; m++) {
                    float d = 0.0f;
#pragma unroll
                    for (int n = 0; n < M2; n++) d = fmaf(b[n], csT[m][p][n], d);
                    s = fmaf(a[m], d, s);
                }
                out[e * 5 + p] = s;
            }
        }
    }
}

extern "C" void kernel_launch(void* const* d_in, const int* in_sizes, int n_in,
                              void* d_out, int out_size)
{
    const float* A = (const float*)d_in[0];
    const float* B = (const float*)d_in[1];
    const float* C = (const float*)d_in[2];
    float* out = (float*)d_out;

    long long n_edges = (long long)in_sizes[0] / M1;
    int blocks = (int)((n_edges + EDGES_PER_CTA - 1) / EDGES_PER_CTA);

    cg_combine_kernel<<<blocks, TPB>>>(A, B, C, out, n_edges);
}

// round 5
// speedup vs baseline: 1.2786x; 1.2786x over previous
#include <cuda_runtime.h>
#include <cstdint>

// out[i,p] = sum_{m,n} A[i,m] * B[i,n] * C[m,n,p]   (M1=M2=MP=5)
//
// Round-5: coalesced smem staging (round-4 idea) with strict register
// discipline to avoid round-4's spills (regs hit the 48 cap -> LDL/STL -> 7x).
//  Phase 1: cp.async (LDGSTS) global->shared, ZERO register staging.
//  Phase 2: 4 edges per thread, processed ONE at a time from shared
//           (live set ~32 regs: a[5]+b[5]+acc[5]+Ccol+addrs).
//  Phase 3: cooperative float4 store-out.
// 41.6KB smem/CTA -> 5 CTAs/SM, 40 warps, reg cap 48.

#define M1 5
#define M2 5
#define MP 5
#define TPB 256
#define EPT 4
#define EDGES_PER_CTA (TPB * EPT)            // 1024
#define CHUNK_FLOATS  (EDGES_PER_CTA * 5)    // 5120
#define CHUNK_F4      (CHUNK_FLOATS / 4)     // 1280
#define F4_PER_THREAD (CHUNK_F4 / TPB)       // 5

__device__ __forceinline__ void cp_async16(uint32_t smem_addr, const void* gptr) {
    asm volatile("cp.async.cg.shared.global [%0], [%1], 16;"
                 :: "r"(smem_addr), "l"(gptr));
}

__global__ __launch_bounds__(TPB, 5)
void cg_combine_kernel(const float* __restrict__ A,
                       const float* __restrict__ B,
                       const float* __restrict__ C,
                       float* __restrict__ out,
                       long long n_edges)
{
    __shared__ __align__(16) float bufA[CHUNK_FLOATS];
    __shared__ __align__(16) float bufB[CHUNK_FLOATS];
    __shared__ float csT[M1][MP][8];         // csT[m][p][n], 32B rows

    int t = threadIdx.x;
    long long cta_base = (long long)blockIdx.x * EDGES_PER_CTA;

    if (t < M1 * M2 * MP) {
        int m = t / 25, n = (t / 5) % 5, p = t % 5;
        csT[m][p][n] = C[t];                 // t = (m*5 + n)*5 + p
    }

    if (cta_base + EDGES_PER_CTA <= n_edges) {
        // ---- phase 1: cp.async coalesced load, no register staging ----
        const float4* gA = reinterpret_cast<const float4*>(A + cta_base * 5);
        const float4* gB = reinterpret_cast<const float4*>(B + cta_base * 5);
        uint32_t sA = (uint32_t)__cvta_generic_to_shared(bufA);
        uint32_t sB = (uint32_t)__cvta_generic_to_shared(bufB);

#pragma unroll
        for (int i = 0; i < F4_PER_THREAD; i++)
            cp_async16(sA + (t + TPB * i) * 16, gA + t + TPB * i);
#pragma unroll
        for (int i = 0; i < F4_PER_THREAD; i++)
            cp_async16(sB + (t + TPB * i) * 16, gB + t + TPB * i);

        asm volatile("cp.async.commit_group;");
        asm volatile("cp.async.wait_group 0;");
        __syncthreads();

        // ---- phase 2: 4 edges, one at a time (low live-register set) ----
#pragma unroll
        for (int j = 0; j < EPT; j++) {
            int e = t + TPB * j;             // lane stride 5 floats: no conflicts

            float a[5], b[5], acc[5];
#pragma unroll
            for (int k = 0; k < 5; k++) {
                a[k] = bufA[e * 5 + k];
                b[k] = bufB[e * 5 + k];
                acc[k] = 0.0f;
            }

#pragma unroll
            for (int m = 0; m < M1; m++) {
                float am = a[m];
#pragma unroll
                for (int p = 0; p < MP; p++) {
                    float4 c03 = *reinterpret_cast<const float4*>(&csT[m][p][0]);
                    float  c4  = csT[m][p][4];

                    float d = c03.x * b[0];
                    d = fmaf(b[1], c03.y, d);
                    d = fmaf(b[2], c03.z, d);
                    d = fmaf(b[3], c03.w, d);
                    d = fmaf(b[4], c4,    d);

                    acc[p] = fmaf(am, d, acc[p]);
                }
            }

            // overwrite this thread's own A slots (thread-private, no hazard)
#pragma unroll
            for (int k = 0; k < 5; k++)
                bufA[e * 5 + k] = acc[k];
        }
        __syncthreads();

        // ---- phase 3: cooperative coalesced store (STG.128 x5) ----
        const float4* s4A = reinterpret_cast<const float4*>(bufA);
        float4* gO = reinterpret_cast<float4*>(out + cta_base * 5);
#pragma unroll
        for (int i = 0; i < F4_PER_THREAD; i++)
            __stcs(gO + t + TPB * i, s4A[t + TPB * i]);
    } else {
        // ---- tail CTA (uniform branch; not taken for N = 16,777,216) ----
        __syncthreads();
        for (long long e = cta_base + t; e < n_edges; e += TPB) {
            float a[5], b[5];
#pragma unroll
            for (int k = 0; k < 5; k++) { a[k] = A[e * 5 + k]; b[k] = B[e * 5 + k]; }
#pragma unroll
            for (int p = 0; p < MP; p++) {
                float s = 0.0f;
#pragma unroll
                for (int m = 0; m < M1; m++) {
                    float d = 0.0f;
#pragma unroll
                    for (int n = 0; n < M2; n++) d = fmaf(b[n], csT[m][p][n], d);
                    s = fmaf(a[m], d, s);
                }
                out[e * 5 + p] = s;
            }
        }
    }
}

extern "C" void kernel_launch(void* const* d_in, const int* in_sizes, int n_in,
                              void* d_out, int out_size)
{
    const float* A = (const float*)d_in[0];
    const float* B = (const float*)d_in[1];
    const float* C = (const float*)d_in[2];
    float* out = (float*)d_out;

    long long n_edges = (long long)in_sizes[0] / M1;
    int blocks = (int)((n_edges + EDGES_PER_CTA - 1) / EDGES_PER_CTA);

    cg_combine_kernel<<<blocks, TPB>>>(A, B, C, out, n_edges);
}

// round 6
// speedup vs baseline: 6.7105x; 5.2484x over previous
#include <cuda_runtime.h>
#include <cstdint>

// out[i,p] = sum_{m,n} A[i,m] * B[i,n] * C[m,n,p]   (M1=M2=MP=5)
//
// Round-6 = round-3's occupancy config (64-reg cap, 4 CTAs/SM — proven
// no-spill for this body) + round-4/5's coalesced staging (cp.async in,
// conflict-free LDS compute, float4 out — kills the 5x L1tex wavefront
// inflation of 20B-strided global access).
// Spill guards: #pragma unroll 1 on the edge loop (rounds 4/5 died because
// ptxas fused all edge iterations under a 48-reg cap), 2 edges/iter for ILP.

#define M1 5
#define M2 5
#define MP 5
#define TPB 256
#define EPT 4
#define EDGES_PER_CTA (TPB * EPT)            // 1024
#define CHUNK_FLOATS  (EDGES_PER_CTA * 5)    // 5120
#define CHUNK_F4      (CHUNK_FLOATS / 4)     // 1280
#define F4_PER_THREAD (CHUNK_F4 / TPB)       // 5

__device__ __forceinline__ void cp_async16(uint32_t smem_addr, const void* gptr) {
    asm volatile("cp.async.cg.shared.global [%0], [%1], 16;"
                 :: "r"(smem_addr), "l"(gptr));
}

__global__ __launch_bounds__(TPB, 4)
void cg_combine_kernel(const float* __restrict__ A,
                       const float* __restrict__ B,
                       const float* __restrict__ C,
                       float* __restrict__ out,
                       long long n_edges)
{
    __shared__ __align__(16) float bufA[CHUNK_FLOATS];
    __shared__ __align__(16) float bufB[CHUNK_FLOATS];
    __shared__ float csT[M1][MP][8];         // csT[m][p][n], 32B rows

    int t = threadIdx.x;
    long long cta_base = (long long)blockIdx.x * EDGES_PER_CTA;

    if (t < M1 * M2 * MP) {
        int m = t / 25, n = (t / 5) % 5, p = t % 5;
        csT[m][p][n] = C[t];                 // t = (m*5 + n)*5 + p
    }

    if (cta_base + EDGES_PER_CTA <= n_edges) {
        // ---- phase 1: cp.async coalesced load, no register staging ----
        const float4* gA = reinterpret_cast<const float4*>(A + cta_base * 5);
        const float4* gB = reinterpret_cast<const float4*>(B + cta_base * 5);
        uint32_t sA = (uint32_t)__cvta_generic_to_shared(bufA);
        uint32_t sB = (uint32_t)__cvta_generic_to_shared(bufB);

#pragma unroll
        for (int i = 0; i < F4_PER_THREAD; i++)
            cp_async16(sA + (t + TPB * i) * 16, gA + t + TPB * i);
#pragma unroll
        for (int i = 0; i < F4_PER_THREAD; i++)
            cp_async16(sB + (t + TPB * i) * 16, gB + t + TPB * i);

        asm volatile("cp.async.commit_group;");
        asm volatile("cp.async.wait_group 0;");
        __syncthreads();

        // ---- phase 2: 2 iterations x 2 edges (unroll 1: keep live set small) ----
#pragma unroll 1
        for (int h = 0; h < EPT / 2; h++) {
            int e0 = t + (TPB * 2) * h;      // lane stride 5 floats: bank-free
            int e1 = e0 + TPB;

            float a0[5], a1[5], b0[5], b1[5], acc0[5], acc1[5];
#pragma unroll
            for (int k = 0; k < 5; k++) {
                a0[k] = bufA[e0 * 5 + k];  a1[k] = bufA[e1 * 5 + k];
                b0[k] = bufB[e0 * 5 + k];  b1[k] = bufB[e1 * 5 + k];
                acc0[k] = 0.0f;            acc1[k] = 0.0f;
            }

#pragma unroll
            for (int m = 0; m < M1; m++) {
                float am0 = a0[m], am1 = a1[m];
#pragma unroll
                for (int p = 0; p < MP; p++) {
                    float4 c03 = *reinterpret_cast<const float4*>(&csT[m][p][0]);
                    float  c4  = csT[m][p][4];

                    float d0 = c03.x * b0[0];
                    float d1 = c03.x * b1[0];
                    d0 = fmaf(b0[1], c03.y, d0);  d1 = fmaf(b1[1], c03.y, d1);
                    d0 = fmaf(b0[2], c03.z, d0);  d1 = fmaf(b1[2], c03.z, d1);
                    d0 = fmaf(b0[3], c03.w, d0);  d1 = fmaf(b1[3], c03.w, d1);
                    d0 = fmaf(b0[4], c4,    d0);  d1 = fmaf(b1[4], c4,    d1);

                    acc0[p] = fmaf(am0, d0, acc0[p]);
                    acc1[p] = fmaf(am1, d1, acc1[p]);
                }
            }

            // overwrite this thread's own A slots (thread-private, no hazard)
#pragma unroll
            for (int k = 0; k < 5; k++) {
                bufA[e0 * 5 + k] = acc0[k];
                bufA[e1 * 5 + k] = acc1[k];
            }
        }
        __syncthreads();

        // ---- phase 3: cooperative coalesced store (STG.128 x5) ----
        const float4* s4A = reinterpret_cast<const float4*>(bufA);
        float4* gO = reinterpret_cast<float4*>(out + cta_base * 5);
#pragma unroll
        for (int i = 0; i < F4_PER_THREAD; i++)
            __stcs(gO + t + TPB * i, s4A[t + TPB * i]);
    } else {
        // ---- tail CTA (uniform branch; not taken for N = 16,777,216) ----
        __syncthreads();
        for (long long e = cta_base + t; e < n_edges; e += TPB) {
            float a[5], b[5];
#pragma unroll
            for (int k = 0; k < 5; k++) { a[k] = A[e * 5 + k]; b[k] = B[e * 5 + k]; }
#pragma unroll
            for (int p = 0; p < MP; p++) {
                float s = 0.0f;
#pragma unroll
                for (int m = 0; m < M1; m++) {
                    float d = 0.0f;
#pragma unroll
                    for (int n = 0; n < M2; n++) d = fmaf(b[n], csT[m][p][n], d);
                    s = fmaf(a[m], d, s);
                }
                out[e * 5 + p] = s;
            }
        }
    }
}

extern "C" void kernel_launch(void* const* d_in, const int* in_sizes, int n_in,
                              void* d_out, int out_size)
{
    const float* A = (const float*)d_in[0];
    const float* B = (const float*)d_in[1];
    const float* C = (const float*)d_in[2];
    float* out = (float*)d_out;

    long long n_edges = (long long)in_sizes[0] / M1;
    int blocks = (int)((n_edges + EDGES_PER_CTA - 1) / EDGES_PER_CTA);

    cg_combine_kernel<<<blocks, TPB>>>(A, B, C, out, n_edges);
}